// round 4
// baseline (speedup 1.0000x reference)
#include <cuda_runtime.h>
#include <cuda_bf16.h>
#include <math_constants.h>

#define NN 50000
#define EE 800000
#define HH 64
#define EDD 32
#define LL 3
#define GG 256
#define OUTD 32
#define SCALE 0.125f

// ---------------- device scratch (no cudaMalloc allowed) ----------------
__device__ float    d_h[NN * HH];          // node features
__device__ float    d_qkvs[NN * 256];      // q|k|v|skip per node
__device__ float    d_etab[LL * 10 * HH];  // per-layer edge tables
__device__ int      d_count[NN];
__device__ int      d_off[NN + 1];
__device__ int      d_wp[NN];
__device__ unsigned d_csr[EE];             // src | attr<<20
__device__ float    d_gate[NN];
__device__ float    d_y[NN * OUTD];

// ---------------- CSR construction ----------------
__global__ void zero_counts() {
    int i = blockIdx.x * blockDim.x + threadIdx.x;
    if (i < NN) d_count[i] = 0;
}

__global__ void hist_kernel(const int* __restrict__ edge_index) {
    int e = blockIdx.x * blockDim.x + threadIdx.x;
    if (e < EE) atomicAdd(&d_count[edge_index[EE + e]], 1);
}

// single-block exclusive scan of d_count -> d_off, d_wp; d_off[NN] = total
__global__ void scan_kernel() {
    __shared__ int wsum[32];
    __shared__ int carry_s;
    int tid = threadIdx.x;
    int lane = tid & 31, wid = tid >> 5;
    if (tid == 0) carry_s = 0;
    __syncthreads();
    for (int base = 0; base < NN; base += 1024) {
        int i = base + tid;
        int v = (i < NN) ? d_count[i] : 0;
        int orig = v;
        #pragma unroll
        for (int o = 1; o < 32; o <<= 1) {
            int t = __shfl_up_sync(0xFFFFFFFFu, v, o);
            if (lane >= o) v += t;
        }
        if (lane == 31) wsum[wid] = v;
        __syncthreads();
        if (wid == 0) {
            int w = wsum[lane];
            #pragma unroll
            for (int o = 1; o < 32; o <<= 1) {
                int t = __shfl_up_sync(0xFFFFFFFFu, w, o);
                if (lane >= o) w += t;
            }
            wsum[lane] = w;
        }
        __syncthreads();
        int woff = (wid > 0) ? wsum[wid - 1] : 0;
        int excl = carry_s + woff + (v - orig);
        if (i < NN) { d_off[i] = excl; d_wp[i] = excl; }
        int chunk_total = wsum[31];
        __syncthreads();
        if (tid == 0) carry_s += chunk_total;
        __syncthreads();
    }
    if (tid == 0) d_off[NN] = carry_s;
}

__global__ void scatter_kernel(const int* __restrict__ edge_index,
                               const int* __restrict__ edge_attr) {
    int e = blockIdx.x * blockDim.x + threadIdx.x;
    if (e < EE) {
        int dst = edge_index[EE + e];
        int pos = atomicAdd(&d_wp[dst], 1);
        d_csr[pos] = (unsigned)edge_index[e] | ((unsigned)edge_attr[e] << 20);
    }
}

// ---------------- edge table precompute: etab[l][a][j] = sum_d edge_emb[a][d]*We[l][d][j]
__global__ void etab_kernel(const float* __restrict__ edge_emb,
                            const float* __restrict__ We) {
    int t = blockIdx.x * blockDim.x + threadIdx.x;
    if (t >= LL * 10 * HH) return;
    int l = t / (10 * HH);
    int a = (t / HH) % 10;
    int j = t % HH;
    float acc = 0.f;
    const float* wb = We + l * EDD * HH;
    const float* eb = edge_emb + a * EDD;
    #pragma unroll
    for (int d = 0; d < EDD; d++) acc += eb[d] * wb[d * HH + j];
    d_etab[t] = acc;
}

// ---------------- initial embedding gather ----------------
__global__ void gather_kernel(const int* __restrict__ x,
                              const float* __restrict__ node_emb) {
    int t = blockIdx.x * blockDim.x + threadIdx.x;
    if (t >= NN * HH) return;
    int i = t >> 6, d = t & 63;
    d_h[t] = node_emb[x[i] * HH + d];
}

// ---------------- fused QKV+skip GEMM: qkvs = h @ [Wq|Wk|Wv|Wskip] + bias
__global__ void __launch_bounds__(256) gemm_qkvs(
    const float* __restrict__ Wq, const float* __restrict__ Wk,
    const float* __restrict__ Wv, const float* __restrict__ Ws,
    const float* __restrict__ bq, const float* __restrict__ bk,
    const float* __restrict__ bv, const float* __restrict__ bs, int l)
{
    __shared__ float hs[64 * 64];
    int c = threadIdx.x;
    int grp = c >> 6, cc = c & 63;
    const float* W; const float* B;
    if (grp == 0)      { W = Wq + l * 4096; B = bq + l * 64; }
    else if (grp == 1) { W = Wk + l * 4096; B = bk + l * 64; }
    else if (grp == 2) { W = Wv + l * 4096; B = bv + l * 64; }
    else               { W = Ws + l * 4096; B = bs + l * 64; }

    float w[64];
    #pragma unroll
    for (int k = 0; k < 64; k++) w[k] = W[k * 64 + cc];
    float bias = B[cc];

    int row0 = blockIdx.x * 64;
    float4* hs4 = (float4*)hs;
    const float4* hg4 = (const float4*)d_h;
    #pragma unroll
    for (int j = 0; j < 4; j++) {
        int idx = threadIdx.x + j * 256;   // float4 index in 64x64 tile
        int r = idx >> 4;
        if (row0 + r < NN) hs4[idx] = hg4[row0 * 16 + idx];
        else hs4[idx] = make_float4(0.f, 0.f, 0.f, 0.f);
    }
    __syncthreads();

    int rmax = min(64, NN - row0);
    for (int r = 0; r < rmax; r++) {
        float acc = bias;
        const float4* hr = (const float4*)(hs + r * 64);
        #pragma unroll
        for (int k4 = 0; k4 < 16; k4++) {
            float4 hv = hr[k4];
            acc += hv.x * w[4 * k4] + hv.y * w[4 * k4 + 1]
                 + hv.z * w[4 * k4 + 2] + hv.w * w[4 * k4 + 3];
        }
        d_qkvs[(row0 + r) * 256 + c] = acc;
    }
}

// ---------------- warp-per-node attention with online softmax ----------------
__global__ void __launch_bounds__(256) attn_kernel(int l) {
    __shared__ float etab[10 * HH];
    for (int i = threadIdx.x; i < 10 * HH; i += blockDim.x)
        etab[i] = d_etab[l * 10 * HH + i];
    __syncthreads();

    int warpid = (blockIdx.x * blockDim.x + threadIdx.x) >> 5;
    int lane = threadIdx.x & 31;
    if (warpid >= NN) return;
    int node = warpid;

    const float* __restrict__ qkvs = d_qkvs;
    float q0 = qkvs[node * 256 + lane];
    float q1 = qkvs[node * 256 + 32 + lane];
    int e0 = d_off[node], e1 = d_off[node + 1];

    float m = -CUDART_INF_F, s = 0.f, a0 = 0.f, a1 = 0.f;
    for (int e = e0; e < e1; e++) {
        unsigned p = __ldg(&d_csr[e]);
        int src = p & 0xFFFFFu;
        int at  = p >> 20;
        float ek0 = etab[at * HH + lane];
        float ek1 = etab[at * HH + 32 + lane];
        const float* kb = qkvs + src * 256;
        float k0v = __ldg(kb + 64 + lane) + ek0;
        float k1v = __ldg(kb + 96 + lane) + ek1;
        float part = q0 * k0v + q1 * k1v;
        #pragma unroll
        for (int o = 16; o > 0; o >>= 1)
            part += __shfl_xor_sync(0xFFFFFFFFu, part, o);
        float alpha = part * SCALE;

        float v0 = __ldg(kb + 128 + lane) + ek0;
        float v1 = __ldg(kb + 160 + lane) + ek1;

        float nm = fmaxf(m, alpha);
        float sc = __expf(m - nm);
        float w  = __expf(alpha - nm);
        s  = s * sc + w;
        a0 = a0 * sc + w * v0;
        a1 = a1 * sc + w * v1;
        m = nm;
    }
    float inv = (s > 0.f) ? (1.f / s) : 0.f;
    float sk0 = qkvs[node * 256 + 192 + lane];
    float sk1 = qkvs[node * 256 + 224 + lane];
    d_h[node * 64 + lane]      = fmaxf(a0 * inv + sk0, 0.f);
    d_h[node * 64 + 32 + lane] = fmaxf(a1 * inv + sk1, 0.f);
}

// ---------------- gate + y per node (warp per node) ----------------
__global__ void __launch_bounds__(256) gate_y_kernel(
    const float* __restrict__ gate_W, const float* __restrict__ gate_b,
    const float* __restrict__ out_W, const float* __restrict__ out_b)
{
    int warpid = (blockIdx.x * blockDim.x + threadIdx.x) >> 5;
    int lane = threadIdx.x & 31;
    if (warpid >= NN) return;
    int node = warpid;
    float h0 = d_h[node * 64 + lane];
    float h1 = d_h[node * 64 + 32 + lane];

    // gate
    float gp = h0 * gate_W[lane] + h1 * gate_W[32 + lane];
    #pragma unroll
    for (int o = 16; o > 0; o >>= 1)
        gp += __shfl_xor_sync(0xFFFFFFFFu, gp, o);
    if (lane == 0) d_gate[node] = gp + gate_b[0];

    // y: col = lane (OUT=32)
    float acc = out_b[lane];
    #pragma unroll
    for (int k = 0; k < 32; k++) {
        float hk = __shfl_sync(0xFFFFFFFFu, h0, k);
        acc += hk * out_W[k * OUTD + lane];
    }
    #pragma unroll
    for (int k = 0; k < 32; k++) {
        float hk = __shfl_sync(0xFFFFFFFFu, h1, k);
        acc += hk * out_W[(32 + k) * OUTD + lane];
    }
    d_y[node * OUTD + lane] = acc;
}

// ---------------- per-graph readout ----------------
__device__ __forceinline__ int lower_bound_dev(const int* a, int n, int key) {
    int lo = 0, hi = n;
    while (lo < hi) {
        int mid = (lo + hi) >> 1;
        if (a[mid] < key) lo = mid + 1; else hi = mid;
    }
    return lo;
}

__global__ void __launch_bounds__(256) readout_kernel(
    const int* __restrict__ batch, float* __restrict__ out)
{
    __shared__ int slo, shi;
    __shared__ float sred[256];
    __shared__ float sm, ssum;
    __shared__ float sacc[8][OUTD];
    int g = blockIdx.x;
    int tid = threadIdx.x;
    int lane = tid & 31, wid = tid >> 5;
    if (tid == 0) {
        slo = lower_bound_dev(batch, NN, g);
        shi = lower_bound_dev(batch, NN, g + 1);
    }
    __syncthreads();
    int lo = slo, hi = shi;

    // block max of gate
    float mx = -CUDART_INF_F;
    for (int n = lo + tid; n < hi; n += 256) mx = fmaxf(mx, d_gate[n]);
    sred[tid] = mx; __syncthreads();
    for (int o = 128; o > 0; o >>= 1) {
        if (tid < o) sred[tid] = fmaxf(sred[tid], sred[tid + o]);
        __syncthreads();
    }
    if (tid == 0) sm = sred[0];
    __syncthreads();
    float mval = sm;

    // block sum of exp
    float sum = 0.f;
    for (int n = lo + tid; n < hi; n += 256) sum += __expf(d_gate[n] - mval);
    sred[tid] = sum; __syncthreads();
    for (int o = 128; o > 0; o >>= 1) {
        if (tid < o) sred[tid] += sred[tid + o];
        __syncthreads();
    }
    if (tid == 0) ssum = sred[0];
    __syncthreads();
    float inv = (ssum > 0.f) ? (1.f / ssum) : 0.f;

    // weighted accumulate: each warp handles a stride-8 subset of nodes,
    // lane = output column; combine across warps in shared.
    float acc = 0.f;
    for (int n = lo + wid; n < hi; n += 8) {
        float w = __expf(d_gate[n] - mval) * inv;
        acc += w * d_y[n * OUTD + lane];
    }
    sacc[wid][lane] = acc;
    __syncthreads();
    if (wid == 0) {
        float a = sacc[0][lane];
        #pragma unroll
        for (int j = 1; j < 8; j++) a += sacc[j][lane];
        out[g * OUTD + lane] = a;
    }
}

// ---------------- launcher ----------------
extern "C" void kernel_launch(void* const* d_in, const int* in_sizes, int n_in,
                              void* d_out, int out_size) {
    const int*   x          = (const int*)d_in[0];
    const int*   edge_index = (const int*)d_in[1];
    const int*   edge_attr  = (const int*)d_in[2];
    const int*   batch      = (const int*)d_in[3];
    const float* node_emb   = (const float*)d_in[4];
    const float* edge_emb   = (const float*)d_in[5];
    const float* Wq         = (const float*)d_in[6];
    const float* Wk         = (const float*)d_in[7];
    const float* Wv         = (const float*)d_in[8];
    const float* We         = (const float*)d_in[9];
    const float* Wskip      = (const float*)d_in[10];
    const float* bq         = (const float*)d_in[11];
    const float* bk         = (const float*)d_in[12];
    const float* bv         = (const float*)d_in[13];
    const float* bskip      = (const float*)d_in[14];
    const float* gate_W     = (const float*)d_in[15];
    const float* gate_b     = (const float*)d_in[16];
    const float* out_W      = (const float*)d_in[17];
    const float* out_b      = (const float*)d_in[18];
    float* out = (float*)d_out;

    // CSR build
    zero_counts<<<(NN + 255) / 256, 256>>>();
    hist_kernel<<<(EE + 255) / 256, 256>>>(edge_index);
    scan_kernel<<<1, 1024>>>();
    scatter_kernel<<<(EE + 255) / 256, 256>>>(edge_index, edge_attr);

    // edge tables + initial embedding
    etab_kernel<<<(LL * 10 * HH + 255) / 256, 256>>>(edge_emb, We);
    gather_kernel<<<(NN * HH + 255) / 256, 256>>>(x, node_emb);

    int attn_blocks = (NN * 32 + 255) / 256;
    for (int l = 0; l < LL; l++) {
        gemm_qkvs<<<(NN + 63) / 64, 256>>>(Wq, Wk, Wv, Wskip, bq, bk, bv, bskip, l);
        attn_kernel<<<attn_blocks, 256>>>(l);
    }

    gate_y_kernel<<<attn_blocks, 256>>>(gate_W, gate_b, out_W, out_b);
    readout_kernel<<<GG, 256>>>(batch, out);
}

// round 9
// speedup vs baseline: 1.0899x; 1.0899x over previous
#include <cuda_runtime.h>
#include <cuda_fp16.h>
#include <cuda_bf16.h>
#include <math_constants.h>

#define NN 50000
#define EE 800000
#define HH 64
#define EDD 32
#define LL 3
#define GG 256
#define OUTD 32
#define SCALE 0.125f

// ---------------- device scratch (no cudaMalloc allowed) ----------------
__device__ float    d_h[NN * HH];          // node features (dim d at pos d)
__device__ float    d_qkvs[NN * 128];      // q[0..63] | skip[64..127] per node
__device__ __half   d_kv16[NN * 128];      // k[0..63] | v[64..127] per node, fp16
__device__ float    d_etab[LL * 10 * HH];  // per-layer edge tables
__device__ int      d_count[NN];
__device__ int      d_off[NN + 1];
__device__ int      d_wp[NN];
__device__ unsigned d_csr[EE];             // src | attr<<20
__device__ float    d_gate[NN];
__device__ float    d_y[NN * OUTD];

// ---------------- CSR construction ----------------
__global__ void zero_counts() {
    int i = blockIdx.x * blockDim.x + threadIdx.x;
    if (i < NN) d_count[i] = 0;
}

__global__ void hist_kernel(const int* __restrict__ edge_index) {
    int e = blockIdx.x * blockDim.x + threadIdx.x;
    if (e < EE) atomicAdd(&d_count[edge_index[EE + e]], 1);
}

// single-block exclusive scan of d_count -> d_off, d_wp; d_off[NN] = total
__global__ void scan_kernel() {
    __shared__ int wsum[32];
    __shared__ int carry_s;
    int tid = threadIdx.x;
    int lane = tid & 31, wid = tid >> 5;
    if (tid == 0) carry_s = 0;
    __syncthreads();
    for (int base = 0; base < NN; base += 1024) {
        int i = base + tid;
        int v = (i < NN) ? d_count[i] : 0;
        int orig = v;
        #pragma unroll
        for (int o = 1; o < 32; o <<= 1) {
            int t = __shfl_up_sync(0xFFFFFFFFu, v, o);
            if (lane >= o) v += t;
        }
        if (lane == 31) wsum[wid] = v;
        __syncthreads();
        if (wid == 0) {
            int w = wsum[lane];
            #pragma unroll
            for (int o = 1; o < 32; o <<= 1) {
                int t = __shfl_up_sync(0xFFFFFFFFu, w, o);
                if (lane >= o) w += t;
            }
            wsum[lane] = w;
        }
        __syncthreads();
        int woff = (wid > 0) ? wsum[wid - 1] : 0;
        int excl = carry_s + woff + (v - orig);
        if (i < NN) { d_off[i] = excl; d_wp[i] = excl; }
        int chunk_total = wsum[31];
        __syncthreads();
        if (tid == 0) carry_s += chunk_total;
        __syncthreads();
    }
    if (tid == 0) d_off[NN] = carry_s;
}

__global__ void scatter_kernel(const int* __restrict__ edge_index,
                               const int* __restrict__ edge_attr) {
    int e = blockIdx.x * blockDim.x + threadIdx.x;
    if (e < EE) {
        int dst = edge_index[EE + e];
        int pos = atomicAdd(&d_wp[dst], 1);
        d_csr[pos] = (unsigned)edge_index[e] | ((unsigned)edge_attr[e] << 20);
    }
}

// ---------------- edge table precompute: etab[l][a][j] = sum_d edge_emb[a][d]*We[l][d][j]
__global__ void etab_kernel(const float* __restrict__ edge_emb,
                            const float* __restrict__ We) {
    int t = blockIdx.x * blockDim.x + threadIdx.x;
    if (t >= LL * 10 * HH) return;
    int l = t / (10 * HH);
    int a = (t / HH) % 10;
    int j = t % HH;
    float acc = 0.f;
    const float* wb = We + l * EDD * HH;
    const float* eb = edge_emb + a * EDD;
    #pragma unroll
    for (int d = 0; d < EDD; d++) acc += eb[d] * wb[d * HH + j];
    d_etab[t] = acc;
}

// ---------------- initial embedding gather ----------------
__global__ void gather_kernel(const int* __restrict__ x,
                              const float* __restrict__ node_emb) {
    int t = blockIdx.x * blockDim.x + threadIdx.x;
    if (t >= NN * HH) return;
    int i = t >> 6, d = t & 63;
    d_h[t] = node_emb[x[i] * HH + d];
}

// ---------------- fused QKV+skip GEMM with packed f32x2 FMA ----------------
// q,skip stored fp32 to d_qkvs; k,v stored fp16 to d_kv16 (only consumer is
// the edge loop). f32x2 packed FMA pairs halve FFMA issue count.
__global__ void __launch_bounds__(256) gemm_qkvs(
    const float* __restrict__ Wq, const float* __restrict__ Wk,
    const float* __restrict__ Wv, const float* __restrict__ Ws,
    const float* __restrict__ bq, const float* __restrict__ bk,
    const float* __restrict__ bv, const float* __restrict__ bs, int l)
{
    __shared__ float hs[64 * 64];
    int c = threadIdx.x;
    int grp = c >> 6, cc = c & 63;
    const float* W; const float* B;
    if (grp == 0)      { W = Wq + l * 4096; B = bq + l * 64; }
    else if (grp == 1) { W = Wk + l * 4096; B = bk + l * 64; }
    else if (grp == 2) { W = Wv + l * 4096; B = bv + l * 64; }
    else               { W = Ws + l * 4096; B = bs + l * 64; }

    // pack weight pairs along K: w2[k] = (W[2k][cc], W[2k+1][cc])
    unsigned long long w2[32];
    #pragma unroll
    for (int k = 0; k < 32; k++) {
        float lo = W[(2 * k) * 64 + cc];
        float hi = W[(2 * k + 1) * 64 + cc];
        asm("mov.b64 %0, {%1, %2};" : "=l"(w2[k]) : "f"(lo), "f"(hi));
    }
    float bias = B[cc];

    int row0 = blockIdx.x * 64;
    float4* hs4 = (float4*)hs;
    const float4* hg4 = (const float4*)d_h;
    #pragma unroll
    for (int j = 0; j < 4; j++) {
        int idx = threadIdx.x + j * 256;   // float4 index in 64x64 tile
        int r = idx >> 4;
        if (row0 + r < NN) hs4[idx] = hg4[row0 * 16 + idx];
        else hs4[idx] = make_float4(0.f, 0.f, 0.f, 0.f);
    }
    __syncthreads();

    int rmax = min(64, NN - row0);
    for (int r = 0; r < rmax; r++) {
        unsigned long long accA = 0ULL, accB = 0ULL;  // (0.f, 0.f) pairs
        const float4* hr = (const float4*)(hs + r * 64);
        #pragma unroll
        for (int k4 = 0; k4 < 16; k4++) {
            float4 hv = hr[k4];
            unsigned long long h2a, h2b;
            asm("mov.b64 %0, {%1, %2};" : "=l"(h2a) : "f"(hv.x), "f"(hv.y));
            asm("mov.b64 %0, {%1, %2};" : "=l"(h2b) : "f"(hv.z), "f"(hv.w));
            asm("fma.rn.f32x2 %0, %1, %2, %0;" : "+l"(accA) : "l"(h2a), "l"(w2[2 * k4]));
            asm("fma.rn.f32x2 %0, %1, %2, %0;" : "+l"(accB) : "l"(h2b), "l"(w2[2 * k4 + 1]));
        }
        float alo, ahi, blo, bhi;
        asm("mov.b64 {%0, %1}, %2;" : "=f"(alo), "=f"(ahi) : "l"(accA));
        asm("mov.b64 {%0, %1}, %2;" : "=f"(blo), "=f"(bhi) : "l"(accB));
        float acc = (alo + ahi) + (blo + bhi) + bias;
        int row = row0 + r;
        if (grp == 0)      d_qkvs[row * 128 + cc]       = acc;            // q
        else if (grp == 3) d_qkvs[row * 128 + 64 + cc]  = acc;            // skip
        else if (grp == 1) d_kv16[row * 128 + cc]       = __float2half(acc); // k
        else               d_kv16[row * 128 + 64 + cc]  = __float2half(acc); // v
    }
}

// ---------------- warp-per-node attention with online softmax ----------------
// Lane j owns dims (2j, 2j+1). k/v read as fp16 half2 (256 B/edge total).
// When last != 0, fuse gate/y readout into the epilogue; skip dead d_h store.
__global__ void __launch_bounds__(256) attn_kernel(
    int l, int last,
    const float* __restrict__ gate_W, const float* __restrict__ gate_b,
    const float* __restrict__ out_W, const float* __restrict__ out_b)
{
    __shared__ float2 etab2[10 * 32];   // [attr][pair j] = (etab[2j], etab[2j+1])
    for (int i = threadIdx.x; i < 10 * 32; i += blockDim.x) {
        etab2[i] = make_float2(d_etab[l * 640 + 2 * i],
                               d_etab[l * 640 + 2 * i + 1]);
    }
    __syncthreads();

    int warpid = (blockIdx.x * blockDim.x + threadIdx.x) >> 5;
    int lane = threadIdx.x & 31;
    if (warpid >= NN) return;
    int node = warpid;

    float2 q01 = ((const float2*)(d_qkvs + node * 128))[lane];
    float q0 = q01.x, q1 = q01.y;
    int e0 = d_off[node], e1 = d_off[node + 1];

    const __half2* __restrict__ kv2 = (const __half2*)d_kv16;

    float m = -CUDART_INF_F, s = 0.f, a0 = 0.f, a1 = 0.f;
    for (int e = e0; e < e1; e++) {
        unsigned p = __ldg(&d_csr[e]);
        int src = p & 0xFFFFFu;
        int at  = p >> 20;
        int base = src * 64;                    // half2 index of node row
        float2 kf = __half22float2(__ldg(kv2 + base + lane));
        float2 vf = __half22float2(__ldg(kv2 + base + 32 + lane));
        float2 ek = etab2[at * 32 + lane];

        float k0v = kf.x + ek.x;
        float k1v = kf.y + ek.y;
        float part = q0 * k0v + q1 * k1v;
        #pragma unroll
        for (int o = 16; o > 0; o >>= 1)
            part += __shfl_xor_sync(0xFFFFFFFFu, part, o);
        float alpha = part * SCALE;

        float v0 = vf.x + ek.x;
        float v1 = vf.y + ek.y;

        float nm = fmaxf(m, alpha);
        float sc = __expf(m - nm);
        float w  = __expf(alpha - nm);
        s  = s * sc + w;
        a0 = a0 * sc + w * v0;
        a1 = a1 * sc + w * v1;
        m = nm;
    }
    float inv = (s > 0.f) ? (1.f / s) : 0.f;
    float2 sk = ((const float2*)(d_qkvs + node * 128 + 64))[lane];
    float h0 = fmaxf(a0 * inv + sk.x, 0.f);   // dim 2*lane
    float h1 = fmaxf(a1 * inv + sk.y, 0.f);   // dim 2*lane+1

    if (!last) {
        ((float2*)(d_h + node * 64))[lane] = make_float2(h0, h1);
    } else {
        // gate = h . gate_W + gate_b  (gate_W dims 2lane, 2lane+1)
        float2 gw = ((const float2*)gate_W)[lane];
        float gp = h0 * gw.x + h1 * gw.y;
        #pragma unroll
        for (int o = 16; o > 0; o >>= 1)
            gp += __shfl_xor_sync(0xFFFFFFFFu, gp, o);
        if (lane == 0) d_gate[node] = gp + gate_b[0];

        // y[col=lane]: dim 2j lives in h0@lane j, dim 2j+1 in h1@lane j
        float acc = out_b[lane];
        #pragma unroll
        for (int j = 0; j < 32; j++) {
            float hj0 = __shfl_sync(0xFFFFFFFFu, h0, j);
            float hj1 = __shfl_sync(0xFFFFFFFFu, h1, j);
            acc += hj0 * out_W[(2 * j) * OUTD + lane]
                 + hj1 * out_W[(2 * j + 1) * OUTD + lane];
        }
        d_y[node * OUTD + lane] = acc;
    }
}

// ---------------- per-graph readout ----------------
__device__ __forceinline__ int lower_bound_dev(const int* a, int n, int key) {
    int lo = 0, hi = n;
    while (lo < hi) {
        int mid = (lo + hi) >> 1;
        if (a[mid] < key) lo = mid + 1; else hi = mid;
    }
    return lo;
}

__global__ void __launch_bounds__(256) readout_kernel(
    const int* __restrict__ batch, float* __restrict__ out)
{
    __shared__ int slo, shi;
    __shared__ float sred[256];
    __shared__ float sm, ssum;
    __shared__ float sacc[8][OUTD];
    int g = blockIdx.x;
    int tid = threadIdx.x;
    int lane = tid & 31, wid = tid >> 5;
    if (tid == 0) {
        slo = lower_bound_dev(batch, NN, g);
        shi = lower_bound_dev(batch, NN, g + 1);
    }
    __syncthreads();
    int lo = slo, hi = shi;

    // block max of gate
    float mx = -CUDART_INF_F;
    for (int n = lo + tid; n < hi; n += 256) mx = fmaxf(mx, d_gate[n]);
    sred[tid] = mx; __syncthreads();
    for (int o = 128; o > 0; o >>= 1) {
        if (tid < o) sred[tid] = fmaxf(sred[tid], sred[tid + o]);
        __syncthreads();
    }
    if (tid == 0) sm = sred[0];
    __syncthreads();
    float mval = sm;

    // block sum of exp
    float sum = 0.f;
    for (int n = lo + tid; n < hi; n += 256) sum += __expf(d_gate[n] - mval);
    sred[tid] = sum; __syncthreads();
    for (int o = 128; o > 0; o >>= 1) {
        if (tid < o) sred[tid] += sred[tid + o];
        __syncthreads();
    }
    if (tid == 0) ssum = sred[0];
    __syncthreads();
    float inv = (ssum > 0.f) ? (1.f / ssum) : 0.f;

    // weighted accumulate: 8 warps stride the node range, lane = out column
    float acc = 0.f;
    for (int n = lo + wid; n < hi; n += 8) {
        float w = __expf(d_gate[n] - mval) * inv;
        acc += w * d_y[n * OUTD + lane];
    }
    sacc[wid][lane] = acc;
    __syncthreads();
    if (wid == 0) {
        float a = sacc[0][lane];
        #pragma unroll
        for (int j = 1; j < 8; j++) a += sacc[j][lane];
        out[g * OUTD + lane] = a;
    }
}

// ---------------- launcher ----------------
extern "C" void kernel_launch(void* const* d_in, const int* in_sizes, int n_in,
                              void* d_out, int out_size) {
    const int*   x          = (const int*)d_in[0];
    const int*   edge_index = (const int*)d_in[1];
    const int*   edge_attr  = (const int*)d_in[2];
    const int*   batch      = (const int*)d_in[3];
    const float* node_emb   = (const float*)d_in[4];
    const float* edge_emb   = (const float*)d_in[5];
    const float* Wq         = (const float*)d_in[6];
    const float* Wk         = (const float*)d_in[7];
    const float* Wv         = (const float*)d_in[8];
    const float* We         = (const float*)d_in[9];
    const float* Wskip      = (const float*)d_in[10];
    const float* bq         = (const float*)d_in[11];
    const float* bk         = (const float*)d_in[12];
    const float* bv         = (const float*)d_in[13];
    const float* bskip      = (const float*)d_in[14];
    const float* gate_W     = (const float*)d_in[15];
    const float* gate_b     = (const float*)d_in[16];
    const float* out_W      = (const float*)d_in[17];
    const float* out_b      = (const float*)d_in[18];
    float* out = (float*)d_out;

    // CSR build
    zero_counts<<<(NN + 255) / 256, 256>>>();
    hist_kernel<<<(EE + 255) / 256, 256>>>(edge_index);
    scan_kernel<<<1, 1024>>>();
    scatter_kernel<<<(EE + 255) / 256, 256>>>(edge_index, edge_attr);

    // edge tables + initial embedding
    etab_kernel<<<(LL * 10 * HH + 255) / 256, 256>>>(edge_emb, We);
    gather_kernel<<<(NN * HH + 255) / 256, 256>>>(x, node_emb);

    int attn_blocks = (NN * 32 + 255) / 256;
    for (int l = 0; l < LL; l++) {
        gemm_qkvs<<<(NN + 63) / 64, 256>>>(Wq, Wk, Wv, Wskip, bq, bk, bv, bskip, l);
        attn_kernel<<<attn_blocks, 256>>>(l, (l == LL - 1) ? 1 : 0,
                                          gate_W, gate_b, out_W, out_b);
    }

    readout_kernel<<<GG, 256>>>(batch, out);
}